// round 4
// baseline (speedup 1.0000x reference)
#include <cuda_runtime.h>

#define BATCH 16
#define NA 3
#define NC 80
#define HH 76
#define WW 76
#define HW (HH * WW)
#define TOTAL (BATCH * NA * HW)
#define BOXES_ELEMS (TOTAL * 4)

__global__ __launch_bounds__(256) void yolo_decode_kernel(
    const float* __restrict__ in, float* __restrict__ out)
{
    int t = blockIdx.x * blockDim.x + threadIdx.x;
    if (t >= TOTAL) return;

    int ba  = t / HW;          // b*NA + a
    int pos = t - ba * HW;     // h*W + w
    int a   = ba % NA;

    const float* __restrict__ p = in + (size_t)ba * (5 + NC) * HW + pos;

    // head channels
    float tx = p[0 * HW];
    float ty = p[1 * HW];
    float tw = p[2 * HW];
    float th = p[3 * HW];
    float tc = p[4 * HW];

    // class logits — batched coalesced loads, kept in registers
    float cls[NC];
#pragma unroll
    for (int c = 0; c < NC; c++) cls[c] = p[(5 + c) * HW];

    // max-stabilized softmax
    float m = cls[0];
#pragma unroll
    for (int c = 1; c < NC; c++) m = fmaxf(m, cls[c]);
    float s = 0.f;
#pragma unroll
    for (int c = 0; c < NC; c++) {
        cls[c] = __expf(cls[c] - m);
        s += cls[c];
    }

    float det   = __fdividef(1.f, 1.f + __expf(-tc));   // sigmoid(conf)
    float scale = __fdividef(det, s);                   // det / sum(exp)

    // box decode
    int gx = pos % WW;
    int gy = pos / WW;
    float sx = __fdividef(1.f, 1.f + __expf(-tx));
    float sy = __fdividef(1.f, 1.f + __expf(-ty));
    float bx = (sx + (float)gx) * (1.0f / WW);
    float by = (sy + (float)gy) * (1.0f / HH);

    // anchors / stride(=8) / grid: w: {12,19,40}/8/76   h: {16,36,28}/8/76
    const float awW[NA] = {1.5f / WW, 2.375f / WW, 5.0f / WW};
    const float ahH[NA] = {2.0f / HH, 4.5f  / HH, 3.5f / HH};
    float bw = __expf(tw) * awW[a];
    float bh = __expf(th) * ahH[a];

    // boxes: (B, A*H*W, 4) — row index == t
    float4* __restrict__ boxes = (float4*)out;
    boxes[t] = make_float4(bx, by, bw, bh);

    // confs: (B, A*H*W, 80) — 320 contiguous bytes per thread
    float4* __restrict__ confs =
        (float4*)(out + (size_t)BOXES_ELEMS + (size_t)t * NC);
#pragma unroll
    for (int c = 0; c < NC; c += 4) {
        confs[c >> 2] = make_float4(cls[c] * scale, cls[c + 1] * scale,
                                    cls[c + 2] * scale, cls[c + 3] * scale);
    }
}

extern "C" void kernel_launch(void* const* d_in, const int* in_sizes, int n_in,
                              void* d_out, int out_size)
{
    const float* in = (const float*)d_in[0];
    float* out = (float*)d_out;
    int blocks = (TOTAL + 255) / 256;
    yolo_decode_kernel<<<blocks, 256>>>(in, out);
}

// round 5
// speedup vs baseline: 1.3259x; 1.3259x over previous
#include <cuda_runtime.h>

#define BATCH 16
#define NA 3
#define NC 80
#define HH 76
#define WW 76
#define HW (HH * WW)
#define TOTAL (BATCH * NA * HW)        /* 277248 */
#define BOXES_ELEMS (TOTAL * 4)
#define LOCS_PER_CTA 64
#define THREADS 256
#define SMEM_STRIDE 84                 /* words; (20*d + q + 4i) mod 32 -> all banks once */

__global__ __launch_bounds__(THREADS) void yolo_decode_kernel(
    const float* __restrict__ in, float* __restrict__ out)
{
    __shared__ __align__(16) float conf_s[LOCS_PER_CTA * SMEM_STRIDE];

    const int tid    = threadIdx.x;
    const int q      = tid & 3;          // class-lane within quad (0..3)
    const int loc_in = tid >> 2;         // 0..63 location within CTA
    const int loc    = blockIdx.x * LOCS_PER_CTA + loc_in;

    const int ba  = loc / HW;            // b*NA + a
    const int pos = loc - ba * HW;       // h*W + w
    const int a   = ba % NA;

    const float* __restrict__ p = in + (size_t)ba * (5 + NC) * HW + pos;

    // 20 class logits per thread: classes q, q+4, ..., q+76.
    // Warp load = 4 adjacent channels x 8 consecutive pos = 4 full 32B sectors.
    float cls[20];
#pragma unroll
    for (int i = 0; i < 20; i++) cls[i] = p[(5 + 4 * i + q) * HW];

    float tc = p[4 * HW];                // det-conf logit (quad lanes share addr)

    // local max, then quad max via butterfly shuffles
    float m = cls[0];
#pragma unroll
    for (int i = 1; i < 20; i++) m = fmaxf(m, cls[i]);
    m = fmaxf(m, __shfl_xor_sync(0xffffffffu, m, 1));
    m = fmaxf(m, __shfl_xor_sync(0xffffffffu, m, 2));

    float s = 0.f;
#pragma unroll
    for (int i = 0; i < 20; i++) {
        cls[i] = __expf(cls[i] - m);
        s += cls[i];
    }
    s += __shfl_xor_sync(0xffffffffu, s, 1);
    s += __shfl_xor_sync(0xffffffffu, s, 2);

    float det   = __fdividef(1.f, 1.f + __expf(-tc));   // sigmoid(conf)
    float scale = __fdividef(det, s);

    // stage conf row in smem (conflict-free: stride 84 + interleaved classes)
    float* row = conf_s + loc_in * SMEM_STRIDE;
#pragma unroll
    for (int i = 0; i < 20; i++) row[4 * i + q] = cls[i] * scale;

    // box decode: one lane per quad; 8 q0-lanes/warp write 128B contiguous
    if (q == 0) {
        float tx = p[0];
        float ty = p[HW];
        float tw = p[2 * HW];
        float th = p[3 * HW];
        int gx = pos % WW;
        int gy = pos / WW;
        float sx = __fdividef(1.f, 1.f + __expf(-tx));
        float sy = __fdividef(1.f, 1.f + __expf(-ty));
        // anchors/stride(=8)/grid: w {12,19,40}/8/76, h {16,36,28}/8/76
        const float awW[NA] = {1.5f / WW, 2.375f / WW, 5.0f / WW};
        const float ahH[NA] = {2.0f / HH, 4.5f  / HH, 3.5f / HH};
        float4 b4 = make_float4((sx + (float)gx) * (1.0f / WW),
                                (sy + (float)gy) * (1.0f / HH),
                                __expf(tw) * awW[a],
                                __expf(th) * ahH[a]);
        ((float4*)out)[loc] = b4;
    }

    __syncthreads();

    // cooperative copy-out: 64 rows x 80 floats = 1280 float4, 5 per thread.
    // consecutive threads -> consecutive float4 -> warp writes 512B contiguous.
    float4* __restrict__ dst = (float4*)(out + (size_t)BOXES_ELEMS
                               + (size_t)blockIdx.x * (LOCS_PER_CTA * NC));
#pragma unroll
    for (int j = 0; j < 5; j++) {
        int k  = tid + j * THREADS;      // 0..1279
        int r  = k / 20;                 // row (location in CTA)
        int c4 = k - r * 20;             // float4 column within row
        const float4* src = (const float4*)(conf_s + r * SMEM_STRIDE + c4 * 4);
        dst[k] = *src;
    }
}

extern "C" void kernel_launch(void* const* d_in, const int* in_sizes, int n_in,
                              void* d_out, int out_size)
{
    const float* in = (const float*)d_in[0];
    float* out = (float*)d_out;
    int blocks = TOTAL / LOCS_PER_CTA;   // 4332, exact
    yolo_decode_kernel<<<blocks, THREADS>>>(in, out);
}